// round 3
// baseline (speedup 1.0000x reference)
#include <cuda_runtime.h>
#include <math.h>

#define HC 128
#define N2MAX 96000
#define EMAX 768000
#define MAXCELLS 65536
#define MAXPTS 32000

// ---------------- scratch (static device globals; no allocation) ----------------
__device__ __align__(16) float g_A[N2MAX * HC];
__device__ __align__(16) float g_B[N2MAX * HC];
__device__ __align__(16) float g_C[N2MAX * HC];
__device__ float g_dinv[N2MAX];
__device__ float g_tp0[16000 * 3];
__device__ float g_tp1[32000 * 3];
__device__ float g_tp2[96000 * 3];
__device__ int   g_idx[N2MAX * 3];
__device__ float g_d2[N2MAX * 3];

// CSR scratch
__device__ int g_cnt[N2MAX];
__device__ int g_csrStart[N2MAX + 1];
__device__ int g_csrCur[N2MAX];
__device__ int g_esrc[EMAX];

// grid kNN scratch
__device__ unsigned g_bbox0[6];
__device__ unsigned g_bbox1[6];
struct GridParams { float ox, oy, oz, h, invh; int Gx, Gy, Gz, Rmax; };
__device__ GridParams g_gp;
__device__ int g_cellCount[MAXCELLS];
__device__ int g_cellStart[MAXCELLS + 1];
__device__ int g_cursor[MAXCELLS];
__device__ __align__(16) float4 g_spts[MAXPTS];
__device__ int g_sidx[MAXPTS];

// ---------------- helpers ----------------
__device__ __forceinline__ unsigned fkey(float f) {
    unsigned u = __float_as_uint(f);
    return (u & 0x80000000u) ? ~u : (u | 0x80000000u);
}
__device__ __forceinline__ float fdec(unsigned k) {
    return (k & 0x80000000u) ? __uint_as_float(k ^ 0x80000000u) : __uint_as_float(~k);
}
__device__ __forceinline__ float selu_f(float v) {
    const float alpha = 1.6732632423543772f;
    const float scale = 1.0507009873554805f;
    return scale * (v > 0.f ? v : alpha * expm1f(v));
}

// ---------------- grid kNN ----------------

__global__ void initbbox_kernel() {
    int i = threadIdx.x;
    if (i < 6)  g_bbox0[i] = (i < 3) ? 0xFFFFFFFFu : 0u;
    if (i < 6)  g_bbox1[i] = (i < 3) ? 0xFFFFFFFFu : 0u;
}

__global__ void transform_kernel(const float* __restrict__ pos, int n,
                                 float* __restrict__ out, unsigned* bbox) {
    int i = blockIdx.x * blockDim.x + threadIdx.x;
    bool valid = (i < n);
    float x = 0.f, y = 0.f, z = 0.f;
    if (valid) { x = pos[3 * i]; y = pos[3 * i + 1]; z = pos[3 * i + 2]; }
    float nx = x - 0.57735026918962576f * y;
    float s = 1.0f + 0.78571428571428571f * (y / 1.1963f);
    float ox = nx * s, oy = y * s, oz = z * s;
    if (valid) { out[3 * i] = ox; out[3 * i + 1] = oy; out[3 * i + 2] = oz; }
    if (bbox) {
        unsigned kx = valid ? fkey(ox) : 0xFFFFFFFFu;
        unsigned ky = valid ? fkey(oy) : 0xFFFFFFFFu;
        unsigned kz = valid ? fkey(oz) : 0xFFFFFFFFu;
        unsigned mnx = __reduce_min_sync(0xFFFFFFFFu, kx);
        unsigned mny = __reduce_min_sync(0xFFFFFFFFu, ky);
        unsigned mnz = __reduce_min_sync(0xFFFFFFFFu, kz);
        unsigned mxx = __reduce_max_sync(0xFFFFFFFFu, valid ? kx : 0u);
        unsigned mxy = __reduce_max_sync(0xFFFFFFFFu, valid ? ky : 0u);
        unsigned mxz = __reduce_max_sync(0xFFFFFFFFu, valid ? kz : 0u);
        if ((threadIdx.x & 31) == 0) {
            atomicMin(&bbox[0], mnx); atomicMin(&bbox[1], mny); atomicMin(&bbox[2], mnz);
            atomicMax(&bbox[3], mxx); atomicMax(&bbox[4], mxy); atomicMax(&bbox[5], mxz);
        }
    }
}

__global__ void gridparams_kernel(const unsigned* __restrict__ bbox, int np) {
    if (threadIdx.x != 0 || blockIdx.x != 0) return;
    float ox = fdec(bbox[0]), oy = fdec(bbox[1]), oz = fdec(bbox[2]);
    float mx = fdec(bbox[3]), my = fdec(bbox[4]), mz = fdec(bbox[5]);
    float ex = mx - ox, ey = my - oy, ez = mz - oz;
    float em = fmaxf(ex, fmaxf(ey, ez));
    float eps = 1e-4f * em + 1e-6f;
    ox -= eps; oy -= eps; oz -= eps;
    ex += 2.f * eps; ey += 2.f * eps; ez += 2.f * eps;
    int target = np / 2; if (target < 1) target = 1;
    float h = cbrtf(ex * ey * ez / (float)target);
    if (h < 1e-6f) h = 1e-6f;
    int Gx, Gy, Gz;
    for (int it = 0; it < 64; it++) {
        Gx = (int)(ex / h) + 1; Gy = (int)(ey / h) + 1; Gz = (int)(ez / h) + 1;
        if (Gx < 1) Gx = 1; if (Gy < 1) Gy = 1; if (Gz < 1) Gz = 1;
        long long prod = (long long)Gx * Gy * Gz;
        if (prod <= MAXCELLS) break;
        h *= 1.0905f;
    }
    GridParams gp;
    gp.ox = ox; gp.oy = oy; gp.oz = oz; gp.h = h; gp.invh = 1.0f / h;
    gp.Gx = Gx; gp.Gy = Gy; gp.Gz = Gz;
    gp.Rmax = max(Gx, max(Gy, Gz));
    g_gp = gp;
}

__global__ void zerocells_kernel() {
    int i = blockIdx.x * blockDim.x + threadIdx.x;
    if (i < MAXCELLS) g_cellCount[i] = 0;
}

__device__ __forceinline__ int cell_of(float x, float y, float z, const GridParams& gp) {
    int cx = (int)floorf((x - gp.ox) * gp.invh);
    int cy = (int)floorf((y - gp.oy) * gp.invh);
    int cz = (int)floorf((z - gp.oz) * gp.invh);
    cx = min(max(cx, 0), gp.Gx - 1);
    cy = min(max(cy, 0), gp.Gy - 1);
    cz = min(max(cz, 0), gp.Gz - 1);
    return (cz * gp.Gy + cy) * gp.Gx + cx;
}

__global__ void gridcount_kernel(const float* __restrict__ p, int np) {
    int i = blockIdx.x * blockDim.x + threadIdx.x;
    if (i >= np) return;
    GridParams gp = g_gp;
    int c = cell_of(p[3 * i], p[3 * i + 1], p[3 * i + 2], gp);
    atomicAdd(&g_cellCount[c], 1);
}

__global__ void __launch_bounds__(1024) gridscan_kernel() {
    __shared__ int ssum[1024];
    int tid = threadIdx.x;
    const int PER = MAXCELLS / 1024;
    int base = tid * PER;
    int sum = 0;
    for (int i = 0; i < PER; i++) sum += g_cellCount[base + i];
    ssum[tid] = sum;
    __syncthreads();
    for (int off = 1; off < 1024; off <<= 1) {
        int v = (tid >= off) ? ssum[tid - off] : 0;
        __syncthreads();
        ssum[tid] += v;
        __syncthreads();
    }
    int run = ssum[tid] - sum;
    for (int i = 0; i < PER; i++) {
        g_cellStart[base + i] = run;
        g_cursor[base + i] = run;
        run += g_cellCount[base + i];
    }
    if (tid == 1023) g_cellStart[MAXCELLS] = run;
}

__global__ void gridscatter_kernel(const float* __restrict__ p, int np) {
    int i = blockIdx.x * blockDim.x + threadIdx.x;
    if (i >= np) return;
    GridParams gp = g_gp;
    float x = p[3 * i], y = p[3 * i + 1], z = p[3 * i + 2];
    int c = cell_of(x, y, z, gp);
    int pos = atomicAdd(&g_cursor[c], 1);
    float p2 = x * x;
    p2 = fmaf(y, y, p2);
    p2 = fmaf(z, z, p2);
    g_spts[pos] = make_float4(x, y, z, p2);
    g_sidx[pos] = i;
}

#define KNN_SCAN_SPAN(S_, E_)                                                   \
    for (int j_ = (S_); j_ < (E_); j_++) {                                      \
        float4 pt = g_spts[j_];                                                 \
        float dot = qx * pt.x;                                                  \
        dot = fmaf(qy, pt.y, dot);                                              \
        dot = fmaf(qz, pt.z, dot);                                              \
        float d = fmaf(-2.0f, dot, qq) + pt.w;                                  \
        if (d < b2) {                                                           \
            int gi = g_sidx[j_];                                                \
            if (d < b0)      { b2 = b1; i2 = i1; b1 = b0; i1 = i0; b0 = d; i0 = gi; } \
            else if (d < b1) { b2 = b1; i2 = i1; b1 = d; i1 = gi; }             \
            else             { b2 = d; i2 = gi; }                               \
        }                                                                       \
    }

__global__ void __launch_bounds__(128) gridknn_kernel(
    const float* __restrict__ q, int nq,
    int* __restrict__ oidx, float* __restrict__ od2) {
    int qi = blockIdx.x * blockDim.x + threadIdx.x;
    if (qi >= nq) return;
    GridParams gp = g_gp;
    float qx = q[3 * qi], qy = q[3 * qi + 1], qz = q[3 * qi + 2];
    float qq = qx * qx;
    qq = fmaf(qy, qy, qq);
    qq = fmaf(qz, qz, qq);
    int ccx = (int)floorf((qx - gp.ox) * gp.invh);
    int ccy = (int)floorf((qy - gp.oy) * gp.invh);
    int ccz = (int)floorf((qz - gp.oz) * gp.invh);
    ccx = min(max(ccx, 0), gp.Gx - 1);
    ccy = min(max(ccy, 0), gp.Gy - 1);
    ccz = min(max(ccz, 0), gp.Gz - 1);

    float b0 = 1e30f, b1 = 1e30f, b2 = 1e30f;
    int i0 = 0, i1 = 0, i2 = 0;

    {
        int c = (ccz * gp.Gy + ccy) * gp.Gx + ccx;
        int s = g_cellStart[c], e = g_cellStart[c + 1];
        KNN_SCAN_SPAN(s, e);
    }
    for (int r = 1; r <= gp.Rmax; r++) {
        float dm = (float)(r - 1) * gp.h;
        if (b2 <= dm * dm) break;
        for (int dz = -r; dz <= r; dz++) {
            int z = ccz + dz;
            if (z < 0 || z >= gp.Gz) continue;
            bool zface = (dz == -r) || (dz == r);
            for (int dy = -r; dy <= r; dy++) {
                int y = ccy + dy;
                if (y < 0 || y >= gp.Gy) continue;
                bool face = zface || (dy == -r) || (dy == r);
                int rowbase = (z * gp.Gy + y) * gp.Gx;
                if (face) {
                    int x0 = max(ccx - r, 0), x1 = min(ccx + r, gp.Gx - 1);
                    int s = g_cellStart[rowbase + x0], e = g_cellStart[rowbase + x1 + 1];
                    KNN_SCAN_SPAN(s, e);
                } else {
                    int x = ccx - r;
                    if (x >= 0) {
                        int s = g_cellStart[rowbase + x], e = g_cellStart[rowbase + x + 1];
                        KNN_SCAN_SPAN(s, e);
                    }
                    x = ccx + r;
                    if (x < gp.Gx) {
                        int s = g_cellStart[rowbase + x], e = g_cellStart[rowbase + x + 1];
                        KNN_SCAN_SPAN(s, e);
                    }
                }
            }
        }
    }
    oidx[qi * 3] = i0; oidx[qi * 3 + 1] = i1; oidx[qi * 3 + 2] = i2;
    od2[qi * 3] = b0;  od2[qi * 3 + 1] = b1;  od2[qi * 3 + 2] = b2;
}

// ---------------- CSR build ----------------

__global__ void zerocnt_kernel(int n) {
    int i = blockIdx.x * blockDim.x + threadIdx.x;
    if (i < n) g_cnt[i] = 0;
}

__global__ void csrcount_kernel(const int* __restrict__ col, int E) {
    int e = blockIdx.x * blockDim.x + threadIdx.x;
    if (e < E) atomicAdd(&g_cnt[col[e]], 1);
}

__global__ void __launch_bounds__(1024) csrscan_kernel(int n) {
    __shared__ int ssum[1024];
    int tid = threadIdx.x;
    int per = (n + 1023) >> 10;
    int base = tid * per;
    int sum = 0;
    for (int i = 0; i < per; i++) {
        int c = base + i;
        if (c < n) sum += g_cnt[c];
    }
    ssum[tid] = sum;
    __syncthreads();
    for (int off = 1; off < 1024; off <<= 1) {
        int v = (tid >= off) ? ssum[tid - off] : 0;
        __syncthreads();
        ssum[tid] += v;
        __syncthreads();
    }
    int run = ssum[tid] - sum;
    for (int i = 0; i < per; i++) {
        int c = base + i;
        if (c < n) { g_csrStart[c] = run; g_csrCur[c] = run; run += g_cnt[c]; }
    }
    if (tid == 1023) g_csrStart[n] = ssum[1023];
}

__global__ void csrfill_kernel(const int* __restrict__ row, const int* __restrict__ col, int E) {
    int e = blockIdx.x * blockDim.x + threadIdx.x;
    if (e >= E) return;
    int pos = atomicAdd(&g_csrCur[col[e]], 1);
    g_esrc[pos] = row[e];
}

__global__ void dinv_kernel(float* __restrict__ d, int n) {
    int i = blockIdx.x * blockDim.x + threadIdx.x;
    if (i < n) d[i] = rsqrtf((float)g_cnt[i] + 1.0f);
}

// ---------------- dense ops ----------------

// x = selu(latent @ W_lin + b_lin), latent [n,64], W [64,128]
__global__ void linear_selu_kernel(const float* __restrict__ latent, const float* __restrict__ W,
                                   const float* __restrict__ b, int n, float* __restrict__ out) {
    __shared__ float s[64];
    int node = blockIdx.x;
    int tid = threadIdx.x;
    if (tid < 64) s[tid] = latent[node * 64 + tid];
    __syncthreads();
    float acc = b[tid];
#pragma unroll 8
    for (int k = 0; k < 64; k++) acc = fmaf(s[k], W[k * HC + tid], acc);
    out[node * HC + tid] = selu_f(acc);
}

// xw = concat(x, pos) @ W   (x [n,128] already activated, pos [n,3], W [131,128])
__global__ void __launch_bounds__(128) gemm128_kernel(
    const float* __restrict__ x, const float* __restrict__ pos,
    const float* __restrict__ W, int n, float* __restrict__ xw) {
    const int NT = 16;
    __shared__ float sIn[NT][132];
    int base = blockIdx.x * NT;
    int tid = threadIdx.x;
    for (int i = tid; i < NT * 132; i += 128) {
        int r = i / 132, c = i - r * 132;
        int node = base + r;
        float v = 0.f;
        if (node < n && c < 131) v = (c < 128) ? x[node * 128 + c] : pos[node * 3 + (c - 128)];
        sIn[r][c] = v;
    }
    __syncthreads();
    float acc[NT];
#pragma unroll
    for (int j = 0; j < NT; j++) acc[j] = 0.f;
#pragma unroll 4
    for (int k = 0; k < 128; k += 4) {
        float w0 = W[k * 128 + tid];
        float w1 = W[(k + 1) * 128 + tid];
        float w2 = W[(k + 2) * 128 + tid];
        float w3 = W[(k + 3) * 128 + tid];
#pragma unroll
        for (int j = 0; j < NT; j++) {
            float4 s4 = *reinterpret_cast<const float4*>(&sIn[j][k]);
            acc[j] = fmaf(s4.x, w0, acc[j]);
            acc[j] = fmaf(s4.y, w1, acc[j]);
            acc[j] = fmaf(s4.z, w2, acc[j]);
            acc[j] = fmaf(s4.w, w3, acc[j]);
        }
    }
#pragma unroll
    for (int k = 128; k < 131; k++) {
        float w = W[k * 128 + tid];
#pragma unroll
        for (int j = 0; j < NT; j++) acc[j] = fmaf(sIn[j][k], w, acc[j]);
    }
#pragma unroll
    for (int j = 0; j < NT; j++) {
        int node = base + j;
        if (node < n) xw[node * 128 + tid] = acc[j];
    }
}

// gather conv: out[c] = f( b + dinv[c]^2*xw[c] + dinv[c] * sum_edges dinv[r]*xw[r] )
// one warp per node, lane = 4 channels
__global__ void __launch_bounds__(256) gconv128_kernel(
    const float4* __restrict__ xw4, const float* __restrict__ dinv,
    const int* __restrict__ start, const int* __restrict__ esrc,
    const float* __restrict__ b, int n, float4* __restrict__ out4, int seluflag) {
    int node = blockIdx.x * 8 + (threadIdx.x >> 5);
    int lane = threadIdx.x & 31;
    if (node >= n) return;
    float dc = dinv[node];
    float4 bv = reinterpret_cast<const float4*>(b)[lane];
    float4 xs = xw4[node * 32 + lane];
    float s2 = dc * dc;
    float4 acc;
    acc.x = fmaf(xs.x, s2, bv.x);
    acc.y = fmaf(xs.y, s2, bv.y);
    acc.z = fmaf(xs.z, s2, bv.z);
    acc.w = fmaf(xs.w, s2, bv.w);
    int s = start[node], e = start[node + 1];
    for (int j = s; j < e; j++) {
        int r = esrc[j];
        float nrm = dinv[r] * dc;
        float4 v = xw4[r * 32 + lane];
        acc.x = fmaf(v.x, nrm, acc.x);
        acc.y = fmaf(v.y, nrm, acc.y);
        acc.z = fmaf(v.z, nrm, acc.z);
        acc.w = fmaf(v.w, nrm, acc.w);
    }
    if (seluflag) {
        acc.x = selu_f(acc.x); acc.y = selu_f(acc.y);
        acc.z = selu_f(acc.z); acc.w = selu_f(acc.w);
    }
    out4[node * 32 + lane] = acc;
}

// out[q] = sum_k w_k x[idx_k] / sum w   (x already activated)
__global__ void interp_kernel(const float* __restrict__ x, const int* __restrict__ idx,
                              const float* __restrict__ d2, int nq, float* __restrict__ out) {
    int qi = blockIdx.x * 2 + (threadIdx.x >> 7);
    int c = threadIdx.x & 127;
    if (qi >= nq) return;
    float w0 = 1.0f / fmaxf(d2[qi * 3],     1e-16f);
    float w1 = 1.0f / fmaxf(d2[qi * 3 + 1], 1e-16f);
    float w2 = 1.0f / fmaxf(d2[qi * 3 + 2], 1e-16f);
    int i0 = idx[qi * 3], i1 = idx[qi * 3 + 1], i2 = idx[qi * 3 + 2];
    float num = w0 * x[i0 * 128 + c];
    num = fmaf(w1, x[i1 * 128 + c], num);
    num = fmaf(w2, x[i2 * 128 + c], num);
    out[qi * 128 + c] = num / (w0 + w1 + w2);
}

// final conv GEMM: xw5 = concat(x, pos) @ W4, W4 [131,5]  (x already activated)
__global__ void __launch_bounds__(128) gemm5_kernel(
    const float* __restrict__ x, const float* __restrict__ pos,
    const float* __restrict__ W, int n, float* __restrict__ xw) {
    const int NT = 25;
    __shared__ float sIn[NT][132];
    __shared__ float sW[131 * 5];
    int tid = threadIdx.x;
    for (int i = tid; i < 131 * 5; i += 128) sW[i] = W[i];
    int base = blockIdx.x * NT;
    for (int i = tid; i < NT * 132; i += 128) {
        int r = i / 132, c = i - r * 132;
        int node = base + r;
        float v = 0.f;
        if (node < n && c < 131) v = (c < 128) ? x[node * 128 + c] : pos[node * 3 + (c - 128)];
        sIn[r][c] = v;
    }
    __syncthreads();
    if (tid < 125) {
        int r = tid / 5, c = tid - r * 5;
        int node = base + r;
        if (node < n) {
            float acc = 0.f;
            for (int k = 0; k < 131; k++) acc = fmaf(sIn[r][k], sW[k * 5 + c], acc);
            xw[node * 5 + c] = acc;
        }
    }
}

// gather conv, 5 channels, one thread per node (no activation)
__global__ void gconv5_kernel(
    const float* __restrict__ xw, const float* __restrict__ dinv,
    const int* __restrict__ start, const int* __restrict__ esrc,
    const float* __restrict__ b, int n, float* __restrict__ out) {
    int node = blockIdx.x * blockDim.x + threadIdx.x;
    if (node >= n) return;
    float dc = dinv[node];
    float s2 = dc * dc;
    float acc[5];
#pragma unroll
    for (int c = 0; c < 5; c++) acc[c] = fmaf(xw[node * 5 + c], s2, b[c]);
    int s = start[node], e = start[node + 1];
    for (int j = s; j < e; j++) {
        int r = esrc[j];
        float nrm = dinv[r] * dc;
#pragma unroll
        for (int c = 0; c < 5; c++) acc[c] = fmaf(xw[r * 5 + c], nrm, acc[c]);
    }
#pragma unroll
    for (int c = 0; c < 5; c++) out[node * 5 + c] = acc[c];
}

// ---------------- orchestration ----------------

static inline int cdiv(int a, int b) { return (a + b - 1) / b; }

static void build_grid(const float* tp, int np, const unsigned* bbox) {
    gridparams_kernel<<<1, 32>>>(bbox, np);
    zerocells_kernel<<<cdiv(MAXCELLS, 256), 256>>>();
    gridcount_kernel<<<cdiv(np, 256), 256>>>(tp, np);
    gridscan_kernel<<<1, 1024>>>();
    gridscatter_kernel<<<cdiv(np, 256), 256>>>(tp, np);
}

static void build_csr(const int* eidx, int E, int n, float* dinv) {
    zerocnt_kernel<<<cdiv(n, 256), 256>>>(n);
    csrcount_kernel<<<cdiv(E, 256), 256>>>(eidx + E, E);
    csrscan_kernel<<<1, 1024>>>(n);
    csrfill_kernel<<<cdiv(E, 256), 256>>>(eidx, eidx + E, E);
    dinv_kernel<<<cdiv(n, 256), 256>>>(dinv, n);
}

extern "C" void kernel_launch(void* const* d_in, const int* in_sizes, int n_in,
                              void* d_out, int out_size) {
    const float* latent = (const float*)d_in[0];
    const float* pos0 = (const float*)d_in[1];
    const float* pos1 = (const float*)d_in[2];
    const float* pos2 = (const float*)d_in[3];
    const float* Wlin = (const float*)d_in[4];
    const float* blin = (const float*)d_in[5];
    const float* W0 = (const float*)d_in[6];  const float* b0 = (const float*)d_in[7];
    const float* W1 = (const float*)d_in[8];  const float* b1 = (const float*)d_in[9];
    const float* W2 = (const float*)d_in[10]; const float* b2 = (const float*)d_in[11];
    const float* W3 = (const float*)d_in[12]; const float* b3 = (const float*)d_in[13];
    const float* W4 = (const float*)d_in[14]; const float* b4 = (const float*)d_in[15];
    const int* e0 = (const int*)d_in[16];
    const int* e1 = (const int*)d_in[17];
    const int* e2 = (const int*)d_in[18];
    float* out = (float*)d_out;

    int N0 = in_sizes[1] / 3, N1 = in_sizes[2] / 3, N2 = in_sizes[3] / 3;
    int E0 = in_sizes[16] / 2, E1 = in_sizes[17] / 2, E2 = in_sizes[18] / 2;

    float *A, *B, *C, *dinv, *tp0, *tp1, *tp2, *d2f;
    int *idx, *csrStart, *esrc;
    unsigned *bb0, *bb1;
    cudaGetSymbolAddress((void**)&A, g_A);
    cudaGetSymbolAddress((void**)&B, g_B);
    cudaGetSymbolAddress((void**)&C, g_C);
    cudaGetSymbolAddress((void**)&dinv, g_dinv);
    cudaGetSymbolAddress((void**)&tp0, g_tp0);
    cudaGetSymbolAddress((void**)&tp1, g_tp1);
    cudaGetSymbolAddress((void**)&tp2, g_tp2);
    cudaGetSymbolAddress((void**)&idx, g_idx);
    cudaGetSymbolAddress((void**)&d2f, g_d2);
    cudaGetSymbolAddress((void**)&bb0, g_bbox0);
    cudaGetSymbolAddress((void**)&bb1, g_bbox1);
    cudaGetSymbolAddress((void**)&csrStart, g_csrStart);
    cudaGetSymbolAddress((void**)&esrc, g_esrc);

    // transforms (+ bbox of candidate sets)
    initbbox_kernel<<<1, 32>>>();
    transform_kernel<<<cdiv(N0, 256), 256>>>(pos0, N0, tp0, bb0);
    transform_kernel<<<cdiv(N1, 256), 256>>>(pos1, N1, tp1, bb1);
    transform_kernel<<<cdiv(N2, 256), 256>>>(pos2, N2, tp2, nullptr);

    // x = selu(latent @ Wlin + blin) -> A
    linear_selu_kernel<<<N0, 128>>>(latent, Wlin, blin, N0, A);

    // level-0 CSR (reused for conv0, conv1)
    build_csr(e0, E0, N0, dinv);

    // conv0: gemm A->B(xw), gather -> C (selu)
    gemm128_kernel<<<cdiv(N0, 16), 128>>>(A, pos0, W0, N0, B);
    gconv128_kernel<<<cdiv(N0, 8), 256>>>((const float4*)B, dinv, csrStart, esrc, b0, N0, (float4*)C, 1);

    // conv1: gemm C->B(xw), gather -> A (selu)
    gemm128_kernel<<<cdiv(N0, 16), 128>>>(C, pos0, W1, N0, B);
    gconv128_kernel<<<cdiv(N0, 8), 256>>>((const float4*)B, dinv, csrStart, esrc, b1, N0, (float4*)A, 1);

    // interp 0 -> 1: A[N0] -> B[N1]
    build_grid(tp0, N0, bb0);
    gridknn_kernel<<<cdiv(N1, 128), 128>>>(tp1, N1, idx, d2f);
    interp_kernel<<<cdiv(N1, 2), 256>>>(A, idx, d2f, N1, B);

    // level-1 CSR
    build_csr(e1, E1, N1, dinv);

    // conv2: gemm B->C(xw), gather -> A (selu)
    gemm128_kernel<<<cdiv(N1, 16), 128>>>(B, pos1, W2, N1, C);
    gconv128_kernel<<<cdiv(N1, 8), 256>>>((const float4*)C, dinv, csrStart, esrc, b2, N1, (float4*)A, 1);

    // interp 1 -> 2: A[N1] -> B[N2]
    build_grid(tp1, N1, bb1);
    gridknn_kernel<<<cdiv(N2, 128), 128>>>(tp2, N2, idx, d2f);
    interp_kernel<<<cdiv(N2, 2), 256>>>(A, idx, d2f, N2, B);

    // level-2 CSR (reused for conv3, conv4)
    build_csr(e2, E2, N2, dinv);

    // conv3: gemm B->C(xw), gather -> A (selu)
    gemm128_kernel<<<cdiv(N2, 16), 128>>>(B, pos2, W3, N2, C);
    gconv128_kernel<<<cdiv(N2, 8), 256>>>((const float4*)C, dinv, csrStart, esrc, b3, N2, (float4*)A, 1);

    // conv4 (no activation): gemm5 A->B(xw5), gather -> out
    gemm5_kernel<<<cdiv(N2, 25), 128>>>(A, pos2, W4, N2, B);
    gconv5_kernel<<<cdiv(N2, 256), 256>>>(B, dinv, csrStart, esrc, b4, N2, out);
}

// round 4
// speedup vs baseline: 1.1660x; 1.1660x over previous
#include <cuda_runtime.h>
#include <math.h>

#define HC 128
#define N2MAX 96000
#define MAXCELLS 65536
#define MAXPTS 32000

// ---------------- scratch (static device globals; no allocation) ----------------
__device__ __align__(16) float g_A[N2MAX * HC];
__device__ __align__(16) float g_B[N2MAX * HC];
__device__ __align__(16) float g_C[N2MAX * HC];
__device__ float g_dinv0[16000];
__device__ float g_dinv1[32000];
__device__ float g_dinv2[96000];
__device__ float g_tp0[16000 * 3];
__device__ float g_tp1[32000 * 3];
__device__ float g_tp2[96000 * 3];
__device__ int   g_idx01[32000 * 3];
__device__ float g_d201[32000 * 3];
__device__ int   g_idx12[N2MAX * 3];
__device__ float g_d212[N2MAX * 3];

// grid kNN scratch (used only on the side stream, serialized there)
__device__ unsigned g_bbox0[6];
__device__ unsigned g_bbox1[6];
struct GridParams { float ox, oy, oz, h, invh; int Gx, Gy, Gz, Rmax; };
__device__ GridParams g_gp;
__device__ int g_cellCount[MAXCELLS];
__device__ int g_cellStart[MAXCELLS + 1];
__device__ int g_cursor[MAXCELLS];
__device__ __align__(16) float4 g_spts[MAXPTS];
__device__ int g_sidx[MAXPTS];

// ---------------- helpers ----------------
__device__ __forceinline__ unsigned fkey(float f) {
    unsigned u = __float_as_uint(f);
    return (u & 0x80000000u) ? ~u : (u | 0x80000000u);
}
__device__ __forceinline__ float fdec(unsigned k) {
    return (k & 0x80000000u) ? __uint_as_float(k ^ 0x80000000u) : __uint_as_float(~k);
}
__device__ __forceinline__ float selu_f(float v) {
    const float alpha = 1.6732632423543772f;
    const float scale = 1.0507009873554805f;
    return scale * (v > 0.f ? v : alpha * expm1f(v));
}

// ---------------- grid kNN ----------------

__global__ void initbbox_kernel() {
    int i = threadIdx.x;
    if (i < 6)  g_bbox0[i] = (i < 3) ? 0xFFFFFFFFu : 0u;
    if (i < 6)  g_bbox1[i] = (i < 3) ? 0xFFFFFFFFu : 0u;
}

__global__ void transform_kernel(const float* __restrict__ pos, int n,
                                 float* __restrict__ out, unsigned* bbox) {
    int i = blockIdx.x * blockDim.x + threadIdx.x;
    bool valid = (i < n);
    float x = 0.f, y = 0.f, z = 0.f;
    if (valid) { x = pos[3 * i]; y = pos[3 * i + 1]; z = pos[3 * i + 2]; }
    float nx = x - 0.57735026918962576f * y;
    float s = 1.0f + 0.78571428571428571f * (y / 1.1963f);
    float ox = nx * s, oy = y * s, oz = z * s;
    if (valid) { out[3 * i] = ox; out[3 * i + 1] = oy; out[3 * i + 2] = oz; }
    if (bbox) {
        unsigned kx = valid ? fkey(ox) : 0xFFFFFFFFu;
        unsigned ky = valid ? fkey(oy) : 0xFFFFFFFFu;
        unsigned kz = valid ? fkey(oz) : 0xFFFFFFFFu;
        unsigned mnx = __reduce_min_sync(0xFFFFFFFFu, kx);
        unsigned mny = __reduce_min_sync(0xFFFFFFFFu, ky);
        unsigned mnz = __reduce_min_sync(0xFFFFFFFFu, kz);
        unsigned mxx = __reduce_max_sync(0xFFFFFFFFu, valid ? kx : 0u);
        unsigned mxy = __reduce_max_sync(0xFFFFFFFFu, valid ? ky : 0u);
        unsigned mxz = __reduce_max_sync(0xFFFFFFFFu, valid ? kz : 0u);
        if ((threadIdx.x & 31) == 0) {
            atomicMin(&bbox[0], mnx); atomicMin(&bbox[1], mny); atomicMin(&bbox[2], mnz);
            atomicMax(&bbox[3], mxx); atomicMax(&bbox[4], mxy); atomicMax(&bbox[5], mxz);
        }
    }
}

__global__ void gridparams_kernel(const unsigned* __restrict__ bbox, int np) {
    if (threadIdx.x != 0 || blockIdx.x != 0) return;
    float ox = fdec(bbox[0]), oy = fdec(bbox[1]), oz = fdec(bbox[2]);
    float mx = fdec(bbox[3]), my = fdec(bbox[4]), mz = fdec(bbox[5]);
    float ex = mx - ox, ey = my - oy, ez = mz - oz;
    float em = fmaxf(ex, fmaxf(ey, ez));
    float eps = 1e-4f * em + 1e-6f;
    ox -= eps; oy -= eps; oz -= eps;
    ex += 2.f * eps; ey += 2.f * eps; ez += 2.f * eps;
    int target = np / 2; if (target < 1) target = 1;
    float h = cbrtf(ex * ey * ez / (float)target);
    if (h < 1e-6f) h = 1e-6f;
    int Gx, Gy, Gz;
    for (int it = 0; it < 64; it++) {
        Gx = (int)(ex / h) + 1; Gy = (int)(ey / h) + 1; Gz = (int)(ez / h) + 1;
        if (Gx < 1) Gx = 1; if (Gy < 1) Gy = 1; if (Gz < 1) Gz = 1;
        long long prod = (long long)Gx * Gy * Gz;
        if (prod <= MAXCELLS) break;
        h *= 1.0905f;
    }
    GridParams gp;
    gp.ox = ox; gp.oy = oy; gp.oz = oz; gp.h = h; gp.invh = 1.0f / h;
    gp.Gx = Gx; gp.Gy = Gy; gp.Gz = Gz;
    gp.Rmax = max(Gx, max(Gy, Gz));
    g_gp = gp;
}

__global__ void zerocells_kernel() {
    int i = blockIdx.x * blockDim.x + threadIdx.x;
    if (i < MAXCELLS) g_cellCount[i] = 0;
}

__device__ __forceinline__ int cell_of(float x, float y, float z, const GridParams& gp) {
    int cx = (int)floorf((x - gp.ox) * gp.invh);
    int cy = (int)floorf((y - gp.oy) * gp.invh);
    int cz = (int)floorf((z - gp.oz) * gp.invh);
    cx = min(max(cx, 0), gp.Gx - 1);
    cy = min(max(cy, 0), gp.Gy - 1);
    cz = min(max(cz, 0), gp.Gz - 1);
    return (cz * gp.Gy + cy) * gp.Gx + cx;
}

__global__ void gridcount_kernel(const float* __restrict__ p, int np) {
    int i = blockIdx.x * blockDim.x + threadIdx.x;
    if (i >= np) return;
    GridParams gp = g_gp;
    int c = cell_of(p[3 * i], p[3 * i + 1], p[3 * i + 2], gp);
    atomicAdd(&g_cellCount[c], 1);
}

__global__ void __launch_bounds__(1024) gridscan_kernel() {
    __shared__ int ssum[1024];
    int tid = threadIdx.x;
    const int PER = MAXCELLS / 1024;
    int base = tid * PER;
    int sum = 0;
    for (int i = 0; i < PER; i++) sum += g_cellCount[base + i];
    ssum[tid] = sum;
    __syncthreads();
    for (int off = 1; off < 1024; off <<= 1) {
        int v = (tid >= off) ? ssum[tid - off] : 0;
        __syncthreads();
        ssum[tid] += v;
        __syncthreads();
    }
    int run = ssum[tid] - sum;
    for (int i = 0; i < PER; i++) {
        g_cellStart[base + i] = run;
        g_cursor[base + i] = run;
        run += g_cellCount[base + i];
    }
    if (tid == 1023) g_cellStart[MAXCELLS] = run;
}

__global__ void gridscatter_kernel(const float* __restrict__ p, int np) {
    int i = blockIdx.x * blockDim.x + threadIdx.x;
    if (i >= np) return;
    GridParams gp = g_gp;
    float x = p[3 * i], y = p[3 * i + 1], z = p[3 * i + 2];
    int c = cell_of(x, y, z, gp);
    int pos = atomicAdd(&g_cursor[c], 1);
    float p2 = x * x;
    p2 = fmaf(y, y, p2);
    p2 = fmaf(z, z, p2);
    g_spts[pos] = make_float4(x, y, z, p2);
    g_sidx[pos] = i;
}

#define KNN_SCAN_SPAN(S_, E_)                                                   \
    for (int j_ = (S_); j_ < (E_); j_++) {                                      \
        float4 pt = g_spts[j_];                                                 \
        float dot = qx * pt.x;                                                  \
        dot = fmaf(qy, pt.y, dot);                                              \
        dot = fmaf(qz, pt.z, dot);                                              \
        float d = fmaf(-2.0f, dot, qq) + pt.w;                                  \
        if (d < b2) {                                                           \
            int gi = g_sidx[j_];                                                \
            if (d < b0)      { b2 = b1; i2 = i1; b1 = b0; i1 = i0; b0 = d; i0 = gi; } \
            else if (d < b1) { b2 = b1; i2 = i1; b1 = d; i1 = gi; }             \
            else             { b2 = d; i2 = gi; }                               \
        }                                                                       \
    }

__global__ void __launch_bounds__(128) gridknn_kernel(
    const float* __restrict__ q, int nq,
    int* __restrict__ oidx, float* __restrict__ od2) {
    int qi = blockIdx.x * blockDim.x + threadIdx.x;
    if (qi >= nq) return;
    GridParams gp = g_gp;
    float qx = q[3 * qi], qy = q[3 * qi + 1], qz = q[3 * qi + 2];
    float qq = qx * qx;
    qq = fmaf(qy, qy, qq);
    qq = fmaf(qz, qz, qq);
    int ccx = (int)floorf((qx - gp.ox) * gp.invh);
    int ccy = (int)floorf((qy - gp.oy) * gp.invh);
    int ccz = (int)floorf((qz - gp.oz) * gp.invh);
    ccx = min(max(ccx, 0), gp.Gx - 1);
    ccy = min(max(ccy, 0), gp.Gy - 1);
    ccz = min(max(ccz, 0), gp.Gz - 1);

    float b0 = 1e30f, b1 = 1e30f, b2 = 1e30f;
    int i0 = 0, i1 = 0, i2 = 0;

    {
        int c = (ccz * gp.Gy + ccy) * gp.Gx + ccx;
        int s = g_cellStart[c], e = g_cellStart[c + 1];
        KNN_SCAN_SPAN(s, e);
    }
    for (int r = 1; r <= gp.Rmax; r++) {
        float dm = (float)(r - 1) * gp.h;
        if (b2 <= dm * dm) break;
        for (int dz = -r; dz <= r; dz++) {
            int z = ccz + dz;
            if (z < 0 || z >= gp.Gz) continue;
            bool zface = (dz == -r) || (dz == r);
            for (int dy = -r; dy <= r; dy++) {
                int y = ccy + dy;
                if (y < 0 || y >= gp.Gy) continue;
                bool face = zface || (dy == -r) || (dy == r);
                int rowbase = (z * gp.Gy + y) * gp.Gx;
                if (face) {
                    int x0 = max(ccx - r, 0), x1 = min(ccx + r, gp.Gx - 1);
                    int s = g_cellStart[rowbase + x0], e = g_cellStart[rowbase + x1 + 1];
                    KNN_SCAN_SPAN(s, e);
                } else {
                    int x = ccx - r;
                    if (x >= 0) {
                        int s = g_cellStart[rowbase + x], e = g_cellStart[rowbase + x + 1];
                        KNN_SCAN_SPAN(s, e);
                    }
                    x = ccx + r;
                    if (x < gp.Gx) {
                        int s = g_cellStart[rowbase + x], e = g_cellStart[rowbase + x + 1];
                        KNN_SCAN_SPAN(s, e);
                    }
                }
            }
        }
    }
    oidx[qi * 3] = i0; oidx[qi * 3 + 1] = i1; oidx[qi * 3 + 2] = i2;
    od2[qi * 3] = b0;  od2[qi * 3 + 1] = b1;  od2[qi * 3 + 2] = b2;
}

// ---------------- degree / dinv ----------------

__global__ void fill1_kernel(float* __restrict__ d, int n) {
    int i = blockIdx.x * blockDim.x + threadIdx.x;
    if (i < n) d[i] = 1.0f;
}

__global__ void degcount_kernel(const int* __restrict__ col, int E, float* __restrict__ deg) {
    int e = blockIdx.x * blockDim.x + threadIdx.x;
    if (e < E) atomicAdd(&deg[col[e]], 1.0f);
}

__global__ void dinv_kernel(float* __restrict__ d, int n) {
    int i = blockIdx.x * blockDim.x + threadIdx.x;
    if (i < n) d[i] = rsqrtf(d[i]);
}

// ---------------- dense ops ----------------

// x = selu(latent @ W_lin + b_lin), latent [n,64], W [64,128]
__global__ void linear_selu_kernel(const float* __restrict__ latent, const float* __restrict__ W,
                                   const float* __restrict__ b, int n, float* __restrict__ out) {
    __shared__ float s[64];
    int node = blockIdx.x;
    int tid = threadIdx.x;
    if (tid < 64) s[tid] = latent[node * 64 + tid];
    __syncthreads();
    float acc = b[tid];
#pragma unroll 8
    for (int k = 0; k < 64; k++) acc = fmaf(s[k], W[k * HC + tid], acc);
    out[node * HC + tid] = selu_f(acc);
}

// xw = concat(f(x), pos) @ W ;  acc = xw * dinv^2 + b   (f = selu if seluflag)
__global__ void __launch_bounds__(128) gemm128_kernel(
    const float* __restrict__ x, const float* __restrict__ pos,
    const float* __restrict__ W, const float* __restrict__ dinv,
    const float* __restrict__ b, int n,
    float* __restrict__ xw, float* __restrict__ accout, int seluflag) {
    const int NT = 16;
    __shared__ float sIn[NT][132];
    int base = blockIdx.x * NT;
    int tid = threadIdx.x;
    for (int i = tid; i < NT * 132; i += 128) {
        int r = i / 132, c = i - r * 132;
        int node = base + r;
        float v = 0.f;
        if (node < n && c < 131) {
            if (c < 128) {
                v = x[node * 128 + c];
                if (seluflag) v = selu_f(v);
            } else {
                v = pos[node * 3 + (c - 128)];
            }
        }
        sIn[r][c] = v;
    }
    __syncthreads();
    float acc[NT];
#pragma unroll
    for (int j = 0; j < NT; j++) acc[j] = 0.f;
#pragma unroll 4
    for (int k = 0; k < 128; k += 4) {
        float w0 = W[k * 128 + tid];
        float w1 = W[(k + 1) * 128 + tid];
        float w2 = W[(k + 2) * 128 + tid];
        float w3 = W[(k + 3) * 128 + tid];
#pragma unroll
        for (int j = 0; j < NT; j++) {
            float4 s4 = *reinterpret_cast<const float4*>(&sIn[j][k]);
            acc[j] = fmaf(s4.x, w0, acc[j]);
            acc[j] = fmaf(s4.y, w1, acc[j]);
            acc[j] = fmaf(s4.z, w2, acc[j]);
            acc[j] = fmaf(s4.w, w3, acc[j]);
        }
    }
#pragma unroll
    for (int k = 128; k < 131; k++) {
        float w = W[k * 128 + tid];
#pragma unroll
        for (int j = 0; j < NT; j++) acc[j] = fmaf(sIn[j][k], w, acc[j]);
    }
    float bb = b[tid];
#pragma unroll
    for (int j = 0; j < NT; j++) {
        int node = base + j;
        if (node < n) {
            float s = dinv[node];
            xw[node * 128 + tid] = acc[j];
            accout[node * 128 + tid] = fmaf(acc[j], s * s, bb);
        }
    }
}

// acc[col] += xw[row] * dinv[row]*dinv[col]  over edges, 128 channels (float4 RED)
__global__ void scatter128_kernel(const float4* __restrict__ xw4, const float* __restrict__ dinv,
                                  const int* __restrict__ row, const int* __restrict__ col,
                                  int E, float4* __restrict__ acc4) {
    int gid = blockIdx.x * blockDim.x + threadIdx.x;
    int e = gid >> 5;
    int j = gid & 31;
    if (e >= E) return;
    int r = row[e], c = col[e];
    float nrm = dinv[r] * dinv[c];
    float4 v = xw4[r * 32 + j];
    v.x *= nrm; v.y *= nrm; v.z *= nrm; v.w *= nrm;
    float* dst = (float*)&acc4[c * 32 + j];
    asm volatile("red.global.add.v4.f32 [%0], {%1,%2,%3,%4};"
                 :: "l"(dst), "f"(v.x), "f"(v.y), "f"(v.z), "f"(v.w) : "memory");
}

// out[q] = sum_k w_k selu(x[idx_k]) / sum w
__global__ void interp_kernel(const float* __restrict__ x, const int* __restrict__ idx,
                              const float* __restrict__ d2, int nq, float* __restrict__ out) {
    int qi = blockIdx.x * 2 + (threadIdx.x >> 7);
    int c = threadIdx.x & 127;
    if (qi >= nq) return;
    float w0 = 1.0f / fmaxf(d2[qi * 3],     1e-16f);
    float w1 = 1.0f / fmaxf(d2[qi * 3 + 1], 1e-16f);
    float w2 = 1.0f / fmaxf(d2[qi * 3 + 2], 1e-16f);
    int i0 = idx[qi * 3], i1 = idx[qi * 3 + 1], i2 = idx[qi * 3 + 2];
    float num = w0 * selu_f(x[i0 * 128 + c]);
    num = fmaf(w1, selu_f(x[i1 * 128 + c]), num);
    num = fmaf(w2, selu_f(x[i2 * 128 + c]), num);
    out[qi * 128 + c] = num / (w0 + w1 + w2);
}

// final conv: xw5 = concat(selu(x), pos) @ W4 ; acc = xw5*dinv^2 + b
__global__ void __launch_bounds__(128) gemm5_kernel(
    const float* __restrict__ x, const float* __restrict__ pos,
    const float* __restrict__ W, const float* __restrict__ dinv,
    const float* __restrict__ b, int n,
    float* __restrict__ xw, float* __restrict__ accout, int seluflag) {
    const int NT = 25;
    __shared__ float sIn[NT][132];
    __shared__ float sW[131 * 5];
    int tid = threadIdx.x;
    for (int i = tid; i < 131 * 5; i += 128) sW[i] = W[i];
    int base = blockIdx.x * NT;
    for (int i = tid; i < NT * 132; i += 128) {
        int r = i / 132, c = i - r * 132;
        int node = base + r;
        float v = 0.f;
        if (node < n && c < 131) {
            if (c < 128) {
                v = x[node * 128 + c];
                if (seluflag) v = selu_f(v);
            } else {
                v = pos[node * 3 + (c - 128)];
            }
        }
        sIn[r][c] = v;
    }
    __syncthreads();
    if (tid < 125) {
        int r = tid / 5, c = tid - r * 5;
        int node = base + r;
        if (node < n) {
            float acc = 0.f;
            for (int k = 0; k < 131; k++) acc = fmaf(sIn[r][k], sW[k * 5 + c], acc);
            float s = dinv[node];
            xw[node * 5 + c] = acc;
            accout[node * 5 + c] = fmaf(acc, s * s, b[c]);
        }
    }
}

__global__ void scatter5_kernel(const float* __restrict__ xw, const float* __restrict__ dinv,
                                const int* __restrict__ row, const int* __restrict__ col,
                                int E, float* __restrict__ acc) {
    int gid = blockIdx.x * blockDim.x + threadIdx.x;
    int e = gid / 5;
    int j = gid - e * 5;
    if (e >= E) return;
    int r = row[e], c = col[e];
    atomicAdd(&acc[c * 5 + j], xw[r * 5 + j] * dinv[r] * dinv[c]);
}

// ---------------- orchestration ----------------

static inline int cdiv(int a, int b) { return (a + b - 1) / b; }

extern "C" void kernel_launch(void* const* d_in, const int* in_sizes, int n_in,
                              void* d_out, int out_size) {
    const float* latent = (const float*)d_in[0];
    const float* pos0 = (const float*)d_in[1];
    const float* pos1 = (const float*)d_in[2];
    const float* pos2 = (const float*)d_in[3];
    const float* Wlin = (const float*)d_in[4];
    const float* blin = (const float*)d_in[5];
    const float* W0 = (const float*)d_in[6];  const float* b0 = (const float*)d_in[7];
    const float* W1 = (const float*)d_in[8];  const float* b1 = (const float*)d_in[9];
    const float* W2 = (const float*)d_in[10]; const float* b2 = (const float*)d_in[11];
    const float* W3 = (const float*)d_in[12]; const float* b3 = (const float*)d_in[13];
    const float* W4 = (const float*)d_in[14]; const float* b4 = (const float*)d_in[15];
    const int* e0 = (const int*)d_in[16];
    const int* e1 = (const int*)d_in[17];
    const int* e2 = (const int*)d_in[18];
    float* out = (float*)d_out;

    int N0 = in_sizes[1] / 3, N1 = in_sizes[2] / 3, N2 = in_sizes[3] / 3;
    int E0 = in_sizes[16] / 2, E1 = in_sizes[17] / 2, E2 = in_sizes[18] / 2;

    float *A, *B, *C, *dv0, *dv1, *dv2, *tp0, *tp1, *tp2, *d201, *d212;
    int *idx01, *idx12;
    unsigned *bb0, *bb1;
    cudaGetSymbolAddress((void**)&A, g_A);
    cudaGetSymbolAddress((void**)&B, g_B);
    cudaGetSymbolAddress((void**)&C, g_C);
    cudaGetSymbolAddress((void**)&dv0, g_dinv0);
    cudaGetSymbolAddress((void**)&dv1, g_dinv1);
    cudaGetSymbolAddress((void**)&dv2, g_dinv2);
    cudaGetSymbolAddress((void**)&tp0, g_tp0);
    cudaGetSymbolAddress((void**)&tp1, g_tp1);
    cudaGetSymbolAddress((void**)&tp2, g_tp2);
    cudaGetSymbolAddress((void**)&idx01, g_idx01);
    cudaGetSymbolAddress((void**)&d201, g_d201);
    cudaGetSymbolAddress((void**)&idx12, g_idx12);
    cudaGetSymbolAddress((void**)&d212, g_d212);
    cudaGetSymbolAddress((void**)&bb0, g_bbox0);
    cudaGetSymbolAddress((void**)&bb1, g_bbox1);

    // one-time stream/event setup (first call is the un-captured correctness run)
    static cudaStream_t sSide = nullptr;
    static cudaEvent_t evStart, evD0, evD1, evD2, evK01, evK12, evSideDone;
    if (!sSide) {
        cudaStreamCreateWithFlags(&sSide, cudaStreamNonBlocking);
        cudaEventCreateWithFlags(&evStart, cudaEventDisableTiming);
        cudaEventCreateWithFlags(&evD0, cudaEventDisableTiming);
        cudaEventCreateWithFlags(&evD1, cudaEventDisableTiming);
        cudaEventCreateWithFlags(&evD2, cudaEventDisableTiming);
        cudaEventCreateWithFlags(&evK01, cudaEventDisableTiming);
        cudaEventCreateWithFlags(&evK12, cudaEventDisableTiming);
        cudaEventCreateWithFlags(&evSideDone, cudaEventDisableTiming);
    }

    // ---- fork side stream ----
    cudaEventRecord(evStart, 0);
    cudaStreamWaitEvent(sSide, evStart, 0);

    // side: transforms + bboxes
    initbbox_kernel<<<1, 32, 0, sSide>>>();
    transform_kernel<<<cdiv(N0, 256), 256, 0, sSide>>>(pos0, N0, tp0, bb0);
    transform_kernel<<<cdiv(N1, 256), 256, 0, sSide>>>(pos1, N1, tp1, bb1);
    transform_kernel<<<cdiv(N2, 256), 256, 0, sSide>>>(pos2, N2, tp2, nullptr);

    // side: dinv level 0
    fill1_kernel<<<cdiv(N0, 256), 256, 0, sSide>>>(dv0, N0);
    degcount_kernel<<<cdiv(E0, 256), 256, 0, sSide>>>(e0 + E0, E0, dv0);
    dinv_kernel<<<cdiv(N0, 256), 256, 0, sSide>>>(dv0, N0);
    cudaEventRecord(evD0, sSide);

    // side: grid(level0 points) + knn for interp 0->1
    gridparams_kernel<<<1, 32, 0, sSide>>>(bb0, N0);
    zerocells_kernel<<<cdiv(MAXCELLS, 256), 256, 0, sSide>>>();
    gridcount_kernel<<<cdiv(N0, 256), 256, 0, sSide>>>(tp0, N0);
    gridscan_kernel<<<1, 1024, 0, sSide>>>();
    gridscatter_kernel<<<cdiv(N0, 256), 256, 0, sSide>>>(tp0, N0);
    gridknn_kernel<<<cdiv(N1, 128), 128, 0, sSide>>>(tp1, N1, idx01, d201);
    cudaEventRecord(evK01, sSide);

    // side: dinv level 1
    fill1_kernel<<<cdiv(N1, 256), 256, 0, sSide>>>(dv1, N1);
    degcount_kernel<<<cdiv(E1, 256), 256, 0, sSide>>>(e1 + E1, E1, dv1);
    dinv_kernel<<<cdiv(N1, 256), 256, 0, sSide>>>(dv1, N1);
    cudaEventRecord(evD1, sSide);

    // side: grid(level1 points) + knn for interp 1->2
    gridparams_kernel<<<1, 32, 0, sSide>>>(bb1, N1);
    zerocells_kernel<<<cdiv(MAXCELLS, 256), 256, 0, sSide>>>();
    gridcount_kernel<<<cdiv(N1, 256), 256, 0, sSide>>>(tp1, N1);
    gridscan_kernel<<<1, 1024, 0, sSide>>>();
    gridscatter_kernel<<<cdiv(N1, 256), 256, 0, sSide>>>(tp1, N1);
    gridknn_kernel<<<cdiv(N2, 128), 128, 0, sSide>>>(tp2, N2, idx12, d212);
    cudaEventRecord(evK12, sSide);

    // side: dinv level 2
    fill1_kernel<<<cdiv(N2, 256), 256, 0, sSide>>>(dv2, N2);
    degcount_kernel<<<cdiv(E2, 256), 256, 0, sSide>>>(e2 + E2, E2, dv2);
    dinv_kernel<<<cdiv(N2, 256), 256, 0, sSide>>>(dv2, N2);
    cudaEventRecord(evD2, sSide);
    cudaEventRecord(evSideDone, sSide);

    // ---- main stream: feature pipeline ----
    linear_selu_kernel<<<N0, 128>>>(latent, Wlin, blin, N0, A);

    cudaStreamWaitEvent(0, evD0, 0);
    // conv0: gemm A -> B(xw), C(init); scatter -> C raw
    gemm128_kernel<<<cdiv(N0, 16), 128>>>(A, pos0, W0, dv0, b0, N0, B, C, 0);
    scatter128_kernel<<<cdiv(E0 * 32, 256), 256>>>((const float4*)B, dv0, e0, e0 + E0, E0, (float4*)C);

    // conv1: gemm selu(C) -> B(xw), A(init); scatter -> A raw
    gemm128_kernel<<<cdiv(N0, 16), 128>>>(C, pos0, W1, dv0, b1, N0, B, A, 1);
    scatter128_kernel<<<cdiv(E0 * 32, 256), 256>>>((const float4*)B, dv0, e0, e0 + E0, E0, (float4*)A);

    // interp 0 -> 1: selu(A)[N0] -> B[N1]
    cudaStreamWaitEvent(0, evK01, 0);
    interp_kernel<<<cdiv(N1, 2), 256>>>(A, idx01, d201, N1, B);

    // conv2: gemm B -> C(xw), A(init); scatter -> A raw
    cudaStreamWaitEvent(0, evD1, 0);
    gemm128_kernel<<<cdiv(N1, 16), 128>>>(B, pos1, W2, dv1, b2, N1, C, A, 0);
    scatter128_kernel<<<cdiv(E1 * 32, 256), 256>>>((const float4*)C, dv1, e1, e1 + E1, E1, (float4*)A);

    // interp 1 -> 2: selu(A)[N1] -> B[N2]
    cudaStreamWaitEvent(0, evK12, 0);
    interp_kernel<<<cdiv(N2, 2), 256>>>(A, idx12, d212, N2, B);

    // conv3: gemm B -> C(xw), A(init); scatter -> A raw
    cudaStreamWaitEvent(0, evD2, 0);
    gemm128_kernel<<<cdiv(N2, 16), 128>>>(B, pos2, W3, dv2, b3, N2, C, A, 0);
    scatter128_kernel<<<cdiv(E2 * 32, 256), 256>>>((const float4*)C, dv2, e2, e2 + E2, E2, (float4*)A);

    // conv4 (no activation): gemm5 selu(A) -> C(xw5), out(init); scatter5 -> out
    gemm5_kernel<<<cdiv(N2, 25), 128>>>(A, pos2, W4, dv2, b4, N2, C, out, 1);
    scatter5_kernel<<<cdiv(E2 * 5, 256), 256>>>(C, dv2, e2, e2 + E2, E2, out);

    // join (ensures whole side stream is inside the captured graph's dependency closure)
    cudaStreamWaitEvent(0, evSideDone, 0);
}

// round 6
// speedup vs baseline: 1.3138x; 1.1268x over previous
#include <cuda_runtime.h>
#include <math.h>

#define HC 128
#define N2MAX 96000
#define MAXCELLS 65536
#define MAXPTS 32000

// ---------------- scratch (static device globals; no allocation) ----------------
__device__ __align__(16) float g_A[N2MAX * HC];
__device__ __align__(16) float g_B[N2MAX * HC];
__device__ __align__(16) float g_C[N2MAX * HC];
__device__ float g_dinv0[16000];
__device__ float g_dinv1[32000];
__device__ float g_dinv2[96000];
__device__ float g_tp0[16000 * 3];
__device__ float g_tp1[32000 * 3];
__device__ float g_tp2[96000 * 3];
__device__ int   g_idx01[32000 * 3];
__device__ float g_d201[32000 * 3];
__device__ int   g_idx12[N2MAX * 3];
__device__ float g_d212[N2MAX * 3];

// grid kNN scratch (side stream only, serialized there)
__device__ unsigned g_bbox0[6];
__device__ unsigned g_bbox1[6];
struct GridParams { float ox, oy, oz, h, invh; int Gx, Gy, Gz, Rmax; };
__device__ GridParams g_gp;
__device__ int g_cellCount[MAXCELLS];
__device__ int g_cellStart[MAXCELLS + 1];
__device__ int g_cursor[MAXCELLS];
__device__ __align__(16) float4 g_spts[MAXPTS];
__device__ int g_sidx[MAXPTS];

// ---------------- helpers ----------------
__device__ __forceinline__ unsigned fkey(float f) {
    unsigned u = __float_as_uint(f);
    return (u & 0x80000000u) ? ~u : (u | 0x80000000u);
}
__device__ __forceinline__ float fdec(unsigned k) {
    return (k & 0x80000000u) ? __uint_as_float(k ^ 0x80000000u) : __uint_as_float(~k);
}
__device__ __forceinline__ float selu_f(float v) {
    const float alpha = 1.6732632423543772f;
    const float scale = 1.0507009873554805f;
    return scale * (v > 0.f ? v : alpha * expm1f(v));
}
__device__ __forceinline__ void ffma2(unsigned long long& d, unsigned long long a, unsigned long long b) {
    asm("fma.rn.f32x2 %0, %1, %2, %0;" : "+l"(d) : "l"(a), "l"(b));
}
__device__ __forceinline__ unsigned long long splat2(float w) {
    unsigned long long r;
    asm("mov.b64 %0, {%1, %1};" : "=l"(r) : "f"(w));
    return r;
}
__device__ __forceinline__ void unpack2(unsigned long long v, float& lo, float& hi) {
    asm("mov.b64 {%0, %1}, %2;" : "=f"(lo), "=f"(hi) : "l"(v));
}

// ---------------- grid kNN ----------------

__global__ void initbbox_kernel() {
    int i = threadIdx.x;
    if (i < 6)  g_bbox0[i] = (i < 3) ? 0xFFFFFFFFu : 0u;
    if (i < 6)  g_bbox1[i] = (i < 3) ? 0xFFFFFFFFu : 0u;
}

__global__ void transform_kernel(const float* __restrict__ pos, int n,
                                 float* __restrict__ out, unsigned* bbox) {
    int i = blockIdx.x * blockDim.x + threadIdx.x;
    bool valid = (i < n);
    float x = 0.f, y = 0.f, z = 0.f;
    if (valid) { x = pos[3 * i]; y = pos[3 * i + 1]; z = pos[3 * i + 2]; }
    float nx = x - 0.57735026918962576f * y;
    float s = 1.0f + 0.78571428571428571f * (y / 1.1963f);
    float ox = nx * s, oy = y * s, oz = z * s;
    if (valid) { out[3 * i] = ox; out[3 * i + 1] = oy; out[3 * i + 2] = oz; }
    if (bbox) {
        unsigned kx = valid ? fkey(ox) : 0xFFFFFFFFu;
        unsigned ky = valid ? fkey(oy) : 0xFFFFFFFFu;
        unsigned kz = valid ? fkey(oz) : 0xFFFFFFFFu;
        unsigned mnx = __reduce_min_sync(0xFFFFFFFFu, kx);
        unsigned mny = __reduce_min_sync(0xFFFFFFFFu, ky);
        unsigned mnz = __reduce_min_sync(0xFFFFFFFFu, kz);
        unsigned mxx = __reduce_max_sync(0xFFFFFFFFu, valid ? kx : 0u);
        unsigned mxy = __reduce_max_sync(0xFFFFFFFFu, valid ? ky : 0u);
        unsigned mxz = __reduce_max_sync(0xFFFFFFFFu, valid ? kz : 0u);
        if ((threadIdx.x & 31) == 0) {
            atomicMin(&bbox[0], mnx); atomicMin(&bbox[1], mny); atomicMin(&bbox[2], mnz);
            atomicMax(&bbox[3], mxx); atomicMax(&bbox[4], mxy); atomicMax(&bbox[5], mxz);
        }
    }
}

__global__ void gridparams_kernel(const unsigned* __restrict__ bbox, int np) {
    if (threadIdx.x != 0 || blockIdx.x != 0) return;
    float ox = fdec(bbox[0]), oy = fdec(bbox[1]), oz = fdec(bbox[2]);
    float mx = fdec(bbox[3]), my = fdec(bbox[4]), mz = fdec(bbox[5]);
    float ex = mx - ox, ey = my - oy, ez = mz - oz;
    float em = fmaxf(ex, fmaxf(ey, ez));
    float eps = 1e-4f * em + 1e-6f;
    ox -= eps; oy -= eps; oz -= eps;
    ex += 2.f * eps; ey += 2.f * eps; ez += 2.f * eps;
    int target = np / 2; if (target < 1) target = 1;
    float h = cbrtf(ex * ey * ez / (float)target);
    if (h < 1e-6f) h = 1e-6f;
    int Gx, Gy, Gz;
    for (int it = 0; it < 64; it++) {
        Gx = (int)(ex / h) + 1; Gy = (int)(ey / h) + 1; Gz = (int)(ez / h) + 1;
        if (Gx < 1) Gx = 1; if (Gy < 1) Gy = 1; if (Gz < 1) Gz = 1;
        long long prod = (long long)Gx * Gy * Gz;
        if (prod <= MAXCELLS) break;
        h *= 1.0905f;
    }
    GridParams gp;
    gp.ox = ox; gp.oy = oy; gp.oz = oz; gp.h = h; gp.invh = 1.0f / h;
    gp.Gx = Gx; gp.Gy = Gy; gp.Gz = Gz;
    gp.Rmax = max(Gx, max(Gy, Gz));
    g_gp = gp;
}

__global__ void zerocells_kernel() {
    int i = blockIdx.x * blockDim.x + threadIdx.x;
    if (i < MAXCELLS) g_cellCount[i] = 0;
}

__device__ __forceinline__ int cell_of(float x, float y, float z, const GridParams& gp) {
    int cx = (int)floorf((x - gp.ox) * gp.invh);
    int cy = (int)floorf((y - gp.oy) * gp.invh);
    int cz = (int)floorf((z - gp.oz) * gp.invh);
    cx = min(max(cx, 0), gp.Gx - 1);
    cy = min(max(cy, 0), gp.Gy - 1);
    cz = min(max(cz, 0), gp.Gz - 1);
    return (cz * gp.Gy + cy) * gp.Gx + cx;
}

__global__ void gridcount_kernel(const float* __restrict__ p, int np) {
    int i = blockIdx.x * blockDim.x + threadIdx.x;
    if (i >= np) return;
    GridParams gp = g_gp;
    int c = cell_of(p[3 * i], p[3 * i + 1], p[3 * i + 2], gp);
    atomicAdd(&g_cellCount[c], 1);
}

__global__ void __launch_bounds__(1024) gridscan_kernel() {
    __shared__ int ssum[1024];
    int tid = threadIdx.x;
    const int PER = MAXCELLS / 1024;
    int base = tid * PER;
    int sum = 0;
    for (int i = 0; i < PER; i++) sum += g_cellCount[base + i];
    ssum[tid] = sum;
    __syncthreads();
    for (int off = 1; off < 1024; off <<= 1) {
        int v = (tid >= off) ? ssum[tid - off] : 0;
        __syncthreads();
        ssum[tid] += v;
        __syncthreads();
    }
    int run = ssum[tid] - sum;
    for (int i = 0; i < PER; i++) {
        g_cellStart[base + i] = run;
        g_cursor[base + i] = run;
        run += g_cellCount[base + i];
    }
    if (tid == 1023) g_cellStart[MAXCELLS] = run;
}

__global__ void gridscatter_kernel(const float* __restrict__ p, int np) {
    int i = blockIdx.x * blockDim.x + threadIdx.x;
    if (i >= np) return;
    GridParams gp = g_gp;
    float x = p[3 * i], y = p[3 * i + 1], z = p[3 * i + 2];
    int c = cell_of(x, y, z, gp);
    int pos = atomicAdd(&g_cursor[c], 1);
    float p2 = x * x;
    p2 = fmaf(y, y, p2);
    p2 = fmaf(z, z, p2);
    g_spts[pos] = make_float4(x, y, z, p2);
    g_sidx[pos] = i;
}

#define KNN_SCAN_SPAN(S_, E_)                                                   \
    for (int j_ = (S_); j_ < (E_); j_++) {                                      \
        float4 pt = g_spts[j_];                                                 \
        float dot = qx * pt.x;                                                  \
        dot = fmaf(qy, pt.y, dot);                                              \
        dot = fmaf(qz, pt.z, dot);                                              \
        float d = fmaf(-2.0f, dot, qq) + pt.w;                                  \
        if (d < b2) {                                                           \
            int gi = g_sidx[j_];                                                \
            if (d < b0)      { b2 = b1; i2 = i1; b1 = b0; i1 = i0; b0 = d; i0 = gi; } \
            else if (d < b1) { b2 = b1; i2 = i1; b1 = d; i1 = gi; }             \
            else             { b2 = d; i2 = gi; }                               \
        }                                                                       \
    }

__global__ void __launch_bounds__(128) gridknn_kernel(
    const float* __restrict__ q, int nq,
    int* __restrict__ oidx, float* __restrict__ od2) {
    int qi = blockIdx.x * blockDim.x + threadIdx.x;
    if (qi >= nq) return;
    GridParams gp = g_gp;
    float qx = q[3 * qi], qy = q[3 * qi + 1], qz = q[3 * qi + 2];
    float qq = qx * qx;
    qq = fmaf(qy, qy, qq);
    qq = fmaf(qz, qz, qq);
    int ccx = (int)floorf((qx - gp.ox) * gp.invh);
    int ccy = (int)floorf((qy - gp.oy) * gp.invh);
    int ccz = (int)floorf((qz - gp.oz) * gp.invh);
    ccx = min(max(ccx, 0), gp.Gx - 1);
    ccy = min(max(ccy, 0), gp.Gy - 1);
    ccz = min(max(ccz, 0), gp.Gz - 1);

    float b0 = 1e30f, b1 = 1e30f, b2 = 1e30f;
    int i0 = 0, i1 = 0, i2 = 0;

    {
        int c = (ccz * gp.Gy + ccy) * gp.Gx + ccx;
        int s = g_cellStart[c], e = g_cellStart[c + 1];
        KNN_SCAN_SPAN(s, e);
    }
    for (int r = 1; r <= gp.Rmax; r++) {
        float dm = (float)(r - 1) * gp.h;
        if (b2 <= dm * dm) break;
        for (int dz = -r; dz <= r; dz++) {
            int z = ccz + dz;
            if (z < 0 || z >= gp.Gz) continue;
            bool zface = (dz == -r) || (dz == r);
            for (int dy = -r; dy <= r; dy++) {
                int y = ccy + dy;
                if (y < 0 || y >= gp.Gy) continue;
                bool face = zface || (dy == -r) || (dy == r);
                int rowbase = (z * gp.Gy + y) * gp.Gx;
                if (face) {
                    int x0 = max(ccx - r, 0), x1 = min(ccx + r, gp.Gx - 1);
                    int s = g_cellStart[rowbase + x0], e = g_cellStart[rowbase + x1 + 1];
                    KNN_SCAN_SPAN(s, e);
                } else {
                    int x = ccx - r;
                    if (x >= 0) {
                        int s = g_cellStart[rowbase + x], e = g_cellStart[rowbase + x + 1];
                        KNN_SCAN_SPAN(s, e);
                    }
                    x = ccx + r;
                    if (x < gp.Gx) {
                        int s = g_cellStart[rowbase + x], e = g_cellStart[rowbase + x + 1];
                        KNN_SCAN_SPAN(s, e);
                    }
                }
            }
        }
    }
    oidx[qi * 3] = i0; oidx[qi * 3 + 1] = i1; oidx[qi * 3 + 2] = i2;
    od2[qi * 3] = b0;  od2[qi * 3 + 1] = b1;  od2[qi * 3 + 2] = b2;
}

// ---------------- degree / dinv ----------------

__global__ void fill1_kernel(float* __restrict__ d, int n) {
    int i = blockIdx.x * blockDim.x + threadIdx.x;
    if (i < n) d[i] = 1.0f;
}

__global__ void degcount_kernel(const int* __restrict__ col, int E, float* __restrict__ deg) {
    int e = blockIdx.x * blockDim.x + threadIdx.x;
    if (e < E) atomicAdd(&deg[col[e]], 1.0f);
}

__global__ void dinv_kernel(float* __restrict__ d, int n) {
    int i = blockIdx.x * blockDim.x + threadIdx.x;
    if (i < n) d[i] = rsqrtf(d[i]);
}

// ---------------- dense ops (FFMA2 versions) ----------------

// x = selu(latent @ W_lin + b_lin), latent [n,64], W [64,128]
// block: 256 threads = 128 ch x 2 node-halves; 32 nodes per block
__global__ void __launch_bounds__(256) linear_selu_kernel(
    const float* __restrict__ latent, const float* __restrict__ W,
    const float* __restrict__ b, int n, float* __restrict__ out) {
    const int NT = 32;
    __shared__ __align__(16) float sIn[64][NT + 4];
    int base = blockIdx.x * NT;
    int tid = threadIdx.x;
    for (int i = tid; i < NT * 64; i += 256) {
        int r = i >> 6, c = i & 63;
        int node = base + r;
        sIn[c][r] = (node < n) ? latent[node * 64 + c] : 0.f;
    }
    __syncthreads();
    int ch = tid & 127, half = tid >> 7;
    unsigned long long acc[8];
#pragma unroll
    for (int j = 0; j < 8; j++) acc[j] = 0ULL;
#pragma unroll 4
    for (int k = 0; k < 64; k++) {
        unsigned long long wp = splat2(W[k * 128 + ch]);
        const ulonglong2* row = reinterpret_cast<const ulonglong2*>(&sIn[k][half * 16]);
#pragma unroll
        for (int g = 0; g < 4; g++) {
            ulonglong2 v = row[g];
            ffma2(acc[2 * g], v.x, wp);
            ffma2(acc[2 * g + 1], v.y, wp);
        }
    }
    float bb = b[ch];
#pragma unroll
    for (int j = 0; j < 8; j++) {
        float lo, hi;
        unpack2(acc[j], lo, hi);
        int n0 = base + half * 16 + 2 * j;
        if (n0 < n)     out[n0 * 128 + ch]       = selu_f(lo + bb);
        if (n0 + 1 < n) out[(n0 + 1) * 128 + ch] = selu_f(hi + bb);
    }
}

// xw = concat(f(x), pos) @ W ;  acc = xw * dinv^2 + b   (f = selu if seluflag)
// block: 256 threads = 128 ch x 2 node-halves; 32 nodes per block
__global__ void __launch_bounds__(256) gemm128_kernel(
    const float* __restrict__ x, const float* __restrict__ pos,
    const float* __restrict__ W, const float* __restrict__ dinv,
    const float* __restrict__ b, int n,
    float* __restrict__ xw, float* __restrict__ accout, int seluflag) {
    const int NT = 32;
    __shared__ __align__(16) float sIn[131][NT + 4];
    int base = blockIdx.x * NT;
    int tid = threadIdx.x;
    for (int i = tid; i < NT * 128; i += 256) {
        int r = i >> 7, c = i & 127;
        int node = base + r;
        float v = 0.f;
        if (node < n) {
            v = x[node * 128 + c];
            if (seluflag) v = selu_f(v);
        }
        sIn[c][r] = v;
    }
    for (int i = tid; i < NT * 3; i += 256) {
        int r = i / 3, c = i - r * 3;
        int node = base + r;
        sIn[128 + c][r] = (node < n) ? pos[node * 3 + c] : 0.f;
    }
    __syncthreads();
    int ch = tid & 127, half = tid >> 7;
    unsigned long long acc[8];
#pragma unroll
    for (int j = 0; j < 8; j++) acc[j] = 0ULL;
#pragma unroll 4
    for (int k = 0; k < 131; k++) {
        unsigned long long wp = splat2(W[k * 128 + ch]);
        const ulonglong2* row = reinterpret_cast<const ulonglong2*>(&sIn[k][half * 16]);
#pragma unroll
        for (int g = 0; g < 4; g++) {
            ulonglong2 v = row[g];
            ffma2(acc[2 * g], v.x, wp);
            ffma2(acc[2 * g + 1], v.y, wp);
        }
    }
    float bb = b[ch];
#pragma unroll
    for (int j = 0; j < 8; j++) {
        float lo, hi;
        unpack2(acc[j], lo, hi);
        int n0 = base + half * 16 + 2 * j;
        if (n0 < n) {
            float s = dinv[n0];
            xw[n0 * 128 + ch] = lo;
            accout[n0 * 128 + ch] = fmaf(lo, s * s, bb);
        }
        if (n0 + 1 < n) {
            float s = dinv[n0 + 1];
            xw[(n0 + 1) * 128 + ch] = hi;
            accout[(n0 + 1) * 128 + ch] = fmaf(hi, s * s, bb);
        }
    }
}

// acc[col] += xw[row] * dinv[row]*dinv[col]  over edges, 128 channels (float4 RED)
__global__ void scatter128_kernel(const float4* __restrict__ xw4, const float* __restrict__ dinv,
                                  const int* __restrict__ row, const int* __restrict__ col,
                                  int E, float4* __restrict__ acc4) {
    int gid = blockIdx.x * blockDim.x + threadIdx.x;
    int e = gid >> 5;
    int j = gid & 31;
    if (e >= E) return;
    int r = row[e], c = col[e];
    float nrm = dinv[r] * dinv[c];
    float4 v = xw4[r * 32 + j];
    v.x *= nrm; v.y *= nrm; v.z *= nrm; v.w *= nrm;
    float* dst = (float*)&acc4[c * 32 + j];
    asm volatile("red.global.add.v4.f32 [%0], {%1,%2,%3,%4};"
                 :: "l"(dst), "f"(v.x), "f"(v.y), "f"(v.z), "f"(v.w) : "memory");
}

// out[q] = sum_k w_k selu(x[idx_k]) / sum w
__global__ void interp_kernel(const float* __restrict__ x, const int* __restrict__ idx,
                              const float* __restrict__ d2, int nq, float* __restrict__ out) {
    int qi = blockIdx.x * 2 + (threadIdx.x >> 7);
    int c = threadIdx.x & 127;
    if (qi >= nq) return;
    float w0 = 1.0f / fmaxf(d2[qi * 3],     1e-16f);
    float w1 = 1.0f / fmaxf(d2[qi * 3 + 1], 1e-16f);
    float w2 = 1.0f / fmaxf(d2[qi * 3 + 2], 1e-16f);
    int i0 = idx[qi * 3], i1 = idx[qi * 3 + 1], i2 = idx[qi * 3 + 2];
    float num = w0 * selu_f(x[i0 * 128 + c]);
    num = fmaf(w1, selu_f(x[i1 * 128 + c]), num);
    num = fmaf(w2, selu_f(x[i2 * 128 + c]), num);
    out[qi * 128 + c] = num / (w0 + w1 + w2);
}

// final conv: xw5 = concat(selu(x), pos) @ W4 ; acc = xw5*dinv^2 + b
__global__ void __launch_bounds__(128) gemm5_kernel(
    const float* __restrict__ x, const float* __restrict__ pos,
    const float* __restrict__ W, const float* __restrict__ dinv,
    const float* __restrict__ b, int n,
    float* __restrict__ xw, float* __restrict__ accout, int seluflag) {
    const int NT = 25;
    __shared__ float sIn[NT][132];
    __shared__ float sW[131 * 5];
    int tid = threadIdx.x;
    for (int i = tid; i < 131 * 5; i += 128) sW[i] = W[i];
    int base = blockIdx.x * NT;
    for (int i = tid; i < NT * 132; i += 128) {
        int r = i / 132, c = i - r * 132;
        int node = base + r;
        float v = 0.f;
        if (node < n && c < 131) {
            if (c < 128) {
                v = x[node * 128 + c];
                if (seluflag) v = selu_f(v);
            } else {
                v = pos[node * 3 + (c - 128)];
            }
        }
        sIn[r][c] = v;
    }
    __syncthreads();
    if (tid < 125) {
        int r = tid / 5, c = tid - r * 5;
        int node = base + r;
        if (node < n) {
            float acc = 0.f;
            for (int k = 0; k < 131; k++) acc = fmaf(sIn[r][k], sW[k * 5 + c], acc);
            float s = dinv[node];
            xw[node * 5 + c] = acc;
            accout[node * 5 + c] = fmaf(acc, s * s, b[c]);
        }
    }
}

__global__ void scatter5_kernel(const float* __restrict__ xw, const float* __restrict__ dinv,
                                const int* __restrict__ row, const int* __restrict__ col,
                                int E, float* __restrict__ acc) {
    int gid = blockIdx.x * blockDim.x + threadIdx.x;
    int e = gid / 5;
    int j = gid - e * 5;
    if (e >= E) return;
    int r = row[e], c = col[e];
    atomicAdd(&acc[c * 5 + j], xw[r * 5 + j] * dinv[r] * dinv[c]);
}

// ---------------- orchestration ----------------

static inline int cdiv(int a, int b) { return (a + b - 1) / b; }

extern "C" void kernel_launch(void* const* d_in, const int* in_sizes, int n_in,
                              void* d_out, int out_size) {
    const float* latent = (const float*)d_in[0];
    const float* pos0 = (const float*)d_in[1];
    const float* pos1 = (const float*)d_in[2];
    const float* pos2 = (const float*)d_in[3];
    const float* Wlin = (const float*)d_in[4];
    const float* blin = (const float*)d_in[5];
    const float* W0 = (const float*)d_in[6];  const float* b0 = (const float*)d_in[7];
    const float* W1 = (const float*)d_in[8];  const float* b1 = (const float*)d_in[9];
    const float* W2 = (const float*)d_in[10]; const float* b2 = (const float*)d_in[11];
    const float* W3 = (const float*)d_in[12]; const float* b3 = (const float*)d_in[13];
    const float* W4 = (const float*)d_in[14]; const float* b4 = (const float*)d_in[15];
    const int* e0 = (const int*)d_in[16];
    const int* e1 = (const int*)d_in[17];
    const int* e2 = (const int*)d_in[18];
    float* out = (float*)d_out;

    int N0 = in_sizes[1] / 3, N1 = in_sizes[2] / 3, N2 = in_sizes[3] / 3;
    int E0 = in_sizes[16] / 2, E1 = in_sizes[17] / 2, E2 = in_sizes[18] / 2;

    float *A, *B, *C, *dv0, *dv1, *dv2, *tp0, *tp1, *tp2, *d201, *d212;
    int *idx01, *idx12;
    unsigned *bb0, *bb1;
    cudaGetSymbolAddress((void**)&A, g_A);
    cudaGetSymbolAddress((void**)&B, g_B);
    cudaGetSymbolAddress((void**)&C, g_C);
    cudaGetSymbolAddress((void**)&dv0, g_dinv0);
    cudaGetSymbolAddress((void**)&dv1, g_dinv1);
    cudaGetSymbolAddress((void**)&dv2, g_dinv2);
    cudaGetSymbolAddress((void**)&tp0, g_tp0);
    cudaGetSymbolAddress((void**)&tp1, g_tp1);
    cudaGetSymbolAddress((void**)&tp2, g_tp2);
    cudaGetSymbolAddress((void**)&idx01, g_idx01);
    cudaGetSymbolAddress((void**)&d201, g_d201);
    cudaGetSymbolAddress((void**)&idx12, g_idx12);
    cudaGetSymbolAddress((void**)&d212, g_d212);
    cudaGetSymbolAddress((void**)&bb0, g_bbox0);
    cudaGetSymbolAddress((void**)&bb1, g_bbox1);

    static cudaStream_t sSide = nullptr;
    static cudaEvent_t evStart, evD0, evD1, evD2, evK01, evK12, evSideDone;
    if (!sSide) {
        cudaStreamCreateWithFlags(&sSide, cudaStreamNonBlocking);
        cudaEventCreateWithFlags(&evStart, cudaEventDisableTiming);
        cudaEventCreateWithFlags(&evD0, cudaEventDisableTiming);
        cudaEventCreateWithFlags(&evD1, cudaEventDisableTiming);
        cudaEventCreateWithFlags(&evD2, cudaEventDisableTiming);
        cudaEventCreateWithFlags(&evK01, cudaEventDisableTiming);
        cudaEventCreateWithFlags(&evK12, cudaEventDisableTiming);
        cudaEventCreateWithFlags(&evSideDone, cudaEventDisableTiming);
    }

    // ---- fork side stream ----
    cudaEventRecord(evStart, 0);
    cudaStreamWaitEvent(sSide, evStart, 0);

    // side: dinv level 0 FIRST (conv0's only side dependency)
    fill1_kernel<<<cdiv(N0, 256), 256, 0, sSide>>>(dv0, N0);
    degcount_kernel<<<cdiv(E0, 256), 256, 0, sSide>>>(e0 + E0, E0, dv0);
    dinv_kernel<<<cdiv(N0, 256), 256, 0, sSide>>>(dv0, N0);
    cudaEventRecord(evD0, sSide);

    // side: transforms + bboxes
    initbbox_kernel<<<1, 32, 0, sSide>>>();
    transform_kernel<<<cdiv(N0, 256), 256, 0, sSide>>>(pos0, N0, tp0, bb0);
    transform_kernel<<<cdiv(N1, 256), 256, 0, sSide>>>(pos1, N1, tp1, bb1);
    transform_kernel<<<cdiv(N2, 256), 256, 0, sSide>>>(pos2, N2, tp2, nullptr);

    // side: grid(level0) + knn for interp 0->1
    gridparams_kernel<<<1, 32, 0, sSide>>>(bb0, N0);
    zerocells_kernel<<<cdiv(MAXCELLS, 256), 256, 0, sSide>>>();
    gridcount_kernel<<<cdiv(N0, 256), 256, 0, sSide>>>(tp0, N0);
    gridscan_kernel<<<1, 1024, 0, sSide>>>();
    gridscatter_kernel<<<cdiv(N0, 256), 256, 0, sSide>>>(tp0, N0);
    gridknn_kernel<<<cdiv(N1, 128), 128, 0, sSide>>>(tp1, N1, idx01, d201);
    cudaEventRecord(evK01, sSide);

    // side: dinv level 1
    fill1_kernel<<<cdiv(N1, 256), 256, 0, sSide>>>(dv1, N1);
    degcount_kernel<<<cdiv(E1, 256), 256, 0, sSide>>>(e1 + E1, E1, dv1);
    dinv_kernel<<<cdiv(N1, 256), 256, 0, sSide>>>(dv1, N1);
    cudaEventRecord(evD1, sSide);

    // side: grid(level1) + knn for interp 1->2
    gridparams_kernel<<<1, 32, 0, sSide>>>(bb1, N1);
    zerocells_kernel<<<cdiv(MAXCELLS, 256), 256, 0, sSide>>>();
    gridcount_kernel<<<cdiv(N1, 256), 256, 0, sSide>>>(tp1, N1);
    gridscan_kernel<<<1, 1024, 0, sSide>>>();
    gridscatter_kernel<<<cdiv(N1, 256), 256, 0, sSide>>>(tp1, N1);
    gridknn_kernel<<<cdiv(N2, 128), 128, 0, sSide>>>(tp2, N2, idx12, d212);
    cudaEventRecord(evK12, sSide);

    // side: dinv level 2
    fill1_kernel<<<cdiv(N2, 256), 256, 0, sSide>>>(dv2, N2);
    degcount_kernel<<<cdiv(E2, 256), 256, 0, sSide>>>(e2 + E2, E2, dv2);
    dinv_kernel<<<cdiv(N2, 256), 256, 0, sSide>>>(dv2, N2);
    cudaEventRecord(evD2, sSide);
    cudaEventRecord(evSideDone, sSide);

    // ---- main stream: feature pipeline ----
    linear_selu_kernel<<<cdiv(N0, 32), 256>>>(latent, Wlin, blin, N0, A);

    cudaStreamWaitEvent(0, evD0, 0);
    // conv0: gemm A -> B(xw), C(init); scatter -> C raw
    gemm128_kernel<<<cdiv(N0, 32), 256>>>(A, pos0, W0, dv0, b0, N0, B, C, 0);
    scatter128_kernel<<<cdiv(E0 * 32, 256), 256>>>((const float4*)B, dv0, e0, e0 + E0, E0, (float4*)C);

    // conv1: gemm selu(C) -> B(xw), A(init); scatter -> A raw
    gemm128_kernel<<<cdiv(N0, 32), 256>>>(C, pos0, W1, dv0, b1, N0, B, A, 1);
    scatter128_kernel<<<cdiv(E0 * 32, 256), 256>>>((const float4*)B, dv0, e0, e0 + E0, E0, (float4*)A);

    // interp 0 -> 1: selu(A)[N0] -> B[N1]
    cudaStreamWaitEvent(0, evK01, 0);
    interp_kernel<<<cdiv(N1, 2), 256>>>(A, idx01, d201, N1, B);

    // conv2: gemm B -> C(xw), A(init); scatter -> A raw
    cudaStreamWaitEvent(0, evD1, 0);
    gemm128_kernel<<<cdiv(N1, 32), 256>>>(B, pos1, W2, dv1, b2, N1, C, A, 0);
    scatter128_kernel<<<cdiv(E1 * 32, 256), 256>>>((const float4*)C, dv1, e1, e1 + E1, E1, (float4*)A);

    // interp 1 -> 2: selu(A)[N1] -> B[N2]
    cudaStreamWaitEvent(0, evK12, 0);
    interp_kernel<<<cdiv(N2, 2), 256>>>(A, idx12, d212, N2, B);

    // conv3: gemm B -> C(xw), A(init); scatter -> A raw
    cudaStreamWaitEvent(0, evD2, 0);
    gemm128_kernel<<<cdiv(N2, 32), 256>>>(B, pos2, W3, dv2, b3, N2, C, A, 0);
    scatter128_kernel<<<cdiv(E2 * 32, 256), 256>>>((const float4*)C, dv2, e2, e2 + E2, E2, (float4*)A);

    // conv4 (no activation): gemm5 selu(A) -> C(xw5), out(init); scatter5 -> out
    gemm5_kernel<<<cdiv(N2, 25), 128>>>(A, pos2, W4, dv2, b4, N2, C, out, 1);
    scatter5_kernel<<<cdiv(E2 * 5, 256), 256>>>(C, dv2, e2, e2 + E2, E2, out);

    // join
    cudaStreamWaitEvent(0, evSideDone, 0);
}